// round 10
// baseline (speedup 1.0000x reference)
#include <cuda_runtime.h>
#include <cstdint>

// Problem constants
#define NB 4
#define NH 16
#define SL 2048
#define HD 64
#define TOPKK 128
#define NEGMAX -3.402823466e38f

#define QK_BLOCKS 136      // triangular 128x128 tiles
#define SEL_BLOCKS 256     // 8 rows per block
#define GRP (QK_BLOCKS + SEL_BLOCKS)

typedef unsigned long long u64;

// 1 GiB score-key scratch: [bh][q][k]
__device__ uint32_t g_keys[(size_t)NB * NH * SL * SL];
__device__ unsigned g_done[NB * NH];

// order-preserving float <-> uint key (monotone increasing)
__device__ __forceinline__ uint32_t f2k(float f) {
    uint32_t b = __float_as_uint(f);
    return b ^ (0x80000000u | (uint32_t)((int32_t)b >> 31));
}
__device__ __forceinline__ float k2f(uint32_t k) {
    uint32_t b = k ^ ((k >> 31) ? 0x80000000u : 0xFFFFFFFFu);
    return __uint_as_float(b);
}

__global__ void init_kernel() { g_done[threadIdx.x] = 0u; }

// ============================================================
// QK body: causal QK^T tile -> score keys (128x128, 8x8/thread)
// ============================================================
#define TILE 128
#define APAD 132
#define FUSED_SMEM (2 * 64 * APAD * 4)   // 67584 B (sel path needs 65536)

__device__ __forceinline__
void qk_body(char* smem_raw, const float* __restrict__ Qg,
             const float* __restrict__ Kg, int bh, int sub)
{
    float* Qs = (float*)smem_raw;
    float* Ks = Qs + 64 * APAD;

    int t = (QK_BLOCKS - 1) - sub;       // heavy tiles first
    int qt = (int)((sqrtf(8.f * (float)t + 1.f) - 1.f) * 0.5f);
    while ((qt + 1) * (qt + 2) / 2 <= t) qt++;
    while (qt * (qt + 1) / 2 > t) qt--;
    int kt = t - qt * (qt + 1) / 2;

    const int qbase = qt * TILE, kbase = kt * TILE;
    const int tid = threadIdx.x;

    const float* Qp = Qg + ((size_t)bh * SL + qbase) * HD;
    const float* Kp = Kg + ((size_t)bh * SL + kbase) * HD;

    #pragma unroll
    for (int it = 0; it < 8; it++) {
        int idx = it * 256 + tid;
        int r = idx >> 4, c = idx & 15;
        float4 v = ((const float4*)(Qp + (size_t)r * HD))[c];
        Qs[(4 * c + 0) * APAD + r] = v.x; Qs[(4 * c + 1) * APAD + r] = v.y;
        Qs[(4 * c + 2) * APAD + r] = v.z; Qs[(4 * c + 3) * APAD + r] = v.w;
        float4 w = ((const float4*)(Kp + (size_t)r * HD))[c];
        Ks[(4 * c + 0) * APAD + r] = w.x; Ks[(4 * c + 1) * APAD + r] = w.y;
        Ks[(4 * c + 2) * APAD + r] = w.z; Ks[(4 * c + 3) * APAD + r] = w.w;
    }
    __syncthreads();

    const int tx = tid & 15, ty = tid >> 4;
    const int q0 = ty * 8, k0 = tx * 8;

    float acc[8][8] = {};
    #pragma unroll 4
    for (int d = 0; d < 64; d++) {
        float a[8], b[8];
        *(float4*)&a[0] = *(const float4*)&Qs[d * APAD + q0];
        *(float4*)&a[4] = *(const float4*)&Qs[d * APAD + q0 + 4];
        *(float4*)&b[0] = *(const float4*)&Ks[d * APAD + k0];
        *(float4*)&b[4] = *(const float4*)&Ks[d * APAD + k0 + 4];
        #pragma unroll
        for (int i = 0; i < 8; i++)
            #pragma unroll
            for (int j = 0; j < 8; j++)
                acc[i][j] = fmaf(a[i], b[j], acc[i][j]);
    }

    const bool diag = (qt == kt);
    #pragma unroll
    for (int i = 0; i < 8; i++) {
        const int qg = qbase + q0 + i;
        uint32_t* row = g_keys + ((size_t)bh * SL + qg) * SL + kbase + k0;
        uint4 lo, hi;
        if (diag) {
            int ql = q0 + i;
            lo.x = f2k((k0     <= ql) ? acc[i][0] : NEGMAX);
            lo.y = f2k((k0 + 1 <= ql) ? acc[i][1] : NEGMAX);
            lo.z = f2k((k0 + 2 <= ql) ? acc[i][2] : NEGMAX);
            lo.w = f2k((k0 + 3 <= ql) ? acc[i][3] : NEGMAX);
            hi.x = f2k((k0 + 4 <= ql) ? acc[i][4] : NEGMAX);
            hi.y = f2k((k0 + 5 <= ql) ? acc[i][5] : NEGMAX);
            hi.z = f2k((k0 + 6 <= ql) ? acc[i][6] : NEGMAX);
            hi.w = f2k((k0 + 7 <= ql) ? acc[i][7] : NEGMAX);
        } else {
            lo.x = f2k(acc[i][0]); lo.y = f2k(acc[i][1]);
            lo.z = f2k(acc[i][2]); lo.w = f2k(acc[i][3]);
            hi.x = f2k(acc[i][4]); hi.y = f2k(acc[i][5]);
            hi.z = f2k(acc[i][6]); hi.w = f2k(acc[i][7]);
        }
        *(uint4*)row = lo;
        *(uint4*)(row + 4) = hi;
    }

    // signal: this bh tile is committed
    __threadfence();
    __syncthreads();
    if (tid == 0) atomicAdd(&g_done[bh], 1u);
}

// ============================================================
// SEL body: streaming top-128 + softmax + PV gather (1 warp/row)
// ============================================================
#define CAP 768
#define PRUNE_HI (CAP - 128)
#define WSTRIDE 2048   // u32 per warp: buf u64[768] | hist 256 | selp u64[128]

__device__ __forceinline__
void bin_scan(const uint32_t* hist, int lane, int& r, int& B) {
    const unsigned FULL = 0xFFFFFFFFu;
    int rev[8]; int s = 0;
    #pragma unroll
    for (int t = 0; t < 8; t++) { rev[t] = (int)hist[255 - (lane * 8 + t)]; s += rev[t]; }
    int inc = s;
    #pragma unroll
    for (int o = 1; o < 32; o <<= 1) {
        int v = __shfl_up_sync(FULL, inc, o);
        if (lane >= o) inc += v;
    }
    int pre = inc - s;
    int cum = pre, Bl = -1, rsub = 0;
    #pragma unroll
    for (int t = 0; t < 8; t++) {
        cum += rev[t];
        if (Bl < 0 && cum >= r) { Bl = 255 - (lane * 8 + t); rsub = r - (cum - rev[t]); }
    }
    unsigned bal = __ballot_sync(FULL, Bl >= 0);
    int src = __ffs(bal) - 1;
    B = __shfl_sync(FULL, Bl, src);
    r = __shfl_sync(FULL, rsub, src);
}

__device__ __forceinline__
void sel_body(char* smem_raw, const float* __restrict__ Vg,
              float* __restrict__ Og, int bh, int sub)
{
    const int tid = threadIdx.x;
    const int warp = tid >> 5, lane = tid & 31;
    const unsigned FULL = 0xFFFFFFFFu;
    const uint32_t lmask = (1u << lane) - 1u;
    const float scale = 0.125f;   // 64^-0.5

    // wait for this bh's QK tiles
    if (tid == 0) {
        unsigned ns = 64;
        while (*(volatile unsigned*)&g_done[bh] < (unsigned)QK_BLOCKS) {
            __nanosleep(ns);
            if (ns < 2048) ns <<= 1;
        }
    }
    __syncthreads();
    __threadfence();

    uint32_t* wmem = (uint32_t*)smem_raw + warp * WSTRIDE;
    u64* buf  = (u64*)wmem;                     // [CAP]
    uint32_t* hist = wmem + 2 * CAP;            // [256]
    u64* selp = (u64*)(wmem + 2 * CAP + 256);   // [128]

    const int qg = ((SEL_BLOCKS - 1) - sub) * 8 + warp;   // heavy rows first
    const int n  = qg + 1;
    const uint32_t* krow = g_keys + ((size_t)bh * SL + qg) * SL;
    const uint4* kr4 = (const uint4*)krow;
    const int n4 = n >> 2;

    // threshold guess: E[s_128] - 5*sigma of the order statistic
    uint32_t T0key = 0;
    if (n >= 512) {
        float lg = log2f((float)n * (1.0f / 128.0f));      // 2..4
        float t0 = 3.75f * lg - 4.5f;
        T0key = f2k(t0);
    }

    int cnt = 0, total = 0;
    u64 vmaxl = 0, vminl = ~(u64)0;
    for (int attempt = 0; ; attempt++) {
        uint32_t Tcur = attempt ? 0u : T0key;
        cnt = 0; total = 0;
        vmaxl = 0; vminl = ~(u64)0;

        for (int base = 0; base < n4; base += 32) {
            int i4 = base + lane;
            bool valid = i4 < n4;
            uint4 x = valid ? kr4[i4] : make_uint4(0, 0, 0, 0);
            #pragma unroll
            for (int c = 0; c < 4; c++) {
                uint32_t k = (c == 0) ? x.x : (c == 1) ? x.y : (c == 2) ? x.z : x.w;
                bool p = valid && (k >= Tcur);
                unsigned bal = __ballot_sync(FULL, p);
                if (p) {
                    int idx = 4 * i4 + c;
                    u64 v = ((u64)k << 32) | (uint32_t)(SL - 1 - idx);
                    buf[cnt + __popc(bal & lmask)] = v;
                    vmaxl = (v > vmaxl) ? v : vmaxl;
                    vminl = (v < vminl) ? v : vminl;
                }
                cnt   += __popc(bal);
                total += __popc(bal);
            }

            if (cnt > PRUNE_HI) {
                // EXACT prune: find buffer's 128th-largest u64 (unique), keep top 128
                u64 prefix = 0, pmask = 0;
                int rr = TOPKK;
                #pragma unroll 1
                for (int level = 7; level >= 0; level--) {
                    #pragma unroll
                    for (int t = 0; t < 8; t++) hist[lane + 32 * t] = 0;
                    __syncwarp();
                    for (int b2 = 0; b2 < cnt; b2 += 32) {
                        int i = b2 + lane;
                        bool valid2 = i < cnt;
                        u64 v = valid2 ? buf[i] : 0;
                        bool ok = valid2 && ((v & pmask) == prefix);
                        uint32_t bb = ok ? (uint32_t)((v >> (8 * level)) & 255) : 0x100u;
                        unsigned grp = __match_any_sync(FULL, bb);
                        if (ok && lane == __ffs(grp) - 1) atomicAdd(&hist[bb], __popc(grp));
                    }
                    __syncwarp();
                    int B; bin_scan(hist, lane, rr, B);
                    prefix |= ((u64)(uint32_t)B) << (8 * level);
                    pmask  |= ((u64)0xFF) << (8 * level);
                }
                const u64 T128 = prefix;
                int nc = 0;
                for (int b2 = 0; b2 < cnt; b2 += 32) {
                    int i = b2 + lane;
                    u64 v = (i < cnt) ? buf[i] : 0;
                    bool keep = (i < cnt) && (v >= T128);
                    unsigned bal = __ballot_sync(FULL, keep);
                    if (keep) buf[nc + __popc(bal & lmask)] = v;
                    nc += __popc(bal);
                }
                __syncwarp();
                cnt = nc;                       // exactly 128
                Tcur = (uint32_t)(T128 >> 32);
            }
        }
        // tail (n % 4)
        {
            int rem = n & 3;
            int i = (n4 << 2) + lane;
            uint32_t k = (lane < rem) ? krow[i] : 0u;
            bool p = (lane < rem) && (k >= Tcur);
            unsigned bal = __ballot_sync(FULL, p);
            if (p) {
                u64 v = ((u64)k << 32) | (uint32_t)(SL - 1 - i);
                buf[cnt + __popc(bal & lmask)] = v;
                vmaxl = (v > vmaxl) ? v : vmaxl;
                vminl = (v < vminl) ? v : vminl;
            }
            cnt   += __popc(bal);
            total += __popc(bal);
        }

        if (n <= TOPKK || total >= TOPKK) break;
    }

    // ---- exact select on the buffer ----
    int selc = 0;
    float dsum = 0.f;

    if (n <= TOPKK) {
        for (int i = lane; i < cnt; i += 32) {
            u64 v = buf[i];
            float w = __expf(k2f((uint32_t)(v >> 32)) * scale);
            int idx = SL - 1 - (int)(uint32_t)(v & 0xFFFFFFFFu);
            selp[i] = ((u64)__float_as_uint(w) << 32) | (uint32_t)idx;
            dsum += w;
        }
        selc = cnt;
    } else {
        // warp-reduce vmax/vmin; skip identical-byte levels
        u64 vmaxW = vmaxl, vminW = vminl;
        #pragma unroll
        for (int o = 16; o > 0; o >>= 1) {
            u64 a = __shfl_xor_sync(FULL, vmaxW, o); if (a > vmaxW) vmaxW = a;
            u64 b = __shfl_xor_sync(FULL, vminW, o); if (b < vminW) vminW = b;
        }
        u64 diff = vmaxW ^ vminW;
        int level0 = (63 - __clzll(diff | 1)) >> 3;                 // 0..7
        const float ref = k2f((uint32_t)(vmaxW >> 32) & 0xFF000000u);

        int r = TOPKK;
        int mm = cnt;

        #pragma unroll 1
        for (int level = level0; level >= 0 && mm != r; level--) {
            #pragma unroll
            for (int t = 0; t < 8; t++) hist[lane + 32 * t] = 0;
            __syncwarp();
            for (int base = 0; base < mm; base += 32) {
                int i = base + lane;
                bool valid = i < mm;
                uint32_t bb = valid ? (uint32_t)((buf[i] >> (8 * level)) & 255) : 0x100u;
                unsigned grp = __match_any_sync(FULL, bb);
                if (valid && lane == __ffs(grp) - 1) atomicAdd(&hist[bb], __popc(grp));
            }
            __syncwarp();
            int B; bin_scan(hist, lane, r, B);

            int nb = 0;
            for (int base = 0; base < mm; base += 32) {
                int i = base + lane;
                u64 v = (i < mm) ? buf[i] : 0;
                int bb = (i < mm) ? (int)((v >> (8 * level)) & 255) : -1;
                bool sure = bb > B;
                bool inb  = bb == B;
                unsigned sbal = __ballot_sync(FULL, sure);
                unsigned bbal = __ballot_sync(FULL, inb);
                if (sure) {
                    float w = __expf((k2f((uint32_t)(v >> 32)) - ref) * scale);
                    int idx = SL - 1 - (int)(uint32_t)(v & 0xFFFFFFFFu);
                    selp[selc + __popc(sbal & lmask)] =
                        ((u64)__float_as_uint(w) << 32) | (uint32_t)idx;
                    dsum += w;
                }
                if (inb) buf[nb + __popc(bbal & lmask)] = v;
                selc += __popc(sbal);
                nb   += __popc(bbal);
            }
            mm = nb;
            __syncwarp();
        }

        for (int i = lane; i < mm; i += 32) {
            u64 v = buf[i];
            float w = __expf((k2f((uint32_t)(v >> 32)) - ref) * scale);
            int idx = SL - 1 - (int)(uint32_t)(v & 0xFFFFFFFFu);
            selp[selc + i] = ((u64)__float_as_uint(w) << 32) | (uint32_t)idx;
            dsum += w;
        }
        selc += mm;
    }

    #pragma unroll
    for (int o = 16; o > 0; o >>= 1) dsum += __shfl_xor_sync(FULL, dsum, o);
    const float inv = 1.f / dsum;
    __syncwarp();

    // ---- PV gather: float2 per lane, 8-deep MLP ----
    const float2* V2 = (const float2*)(Vg + (size_t)bh * SL * HD);
    const int S = selc;
    float ax = 0.f, ay = 0.f;
    int t = 0;
    for (; t + 8 <= S; t += 8) {
        u64 e[8]; float2 vv[8];
        #pragma unroll
        for (int u = 0; u < 8; u++) e[u] = selp[t + u];
        #pragma unroll
        for (int u = 0; u < 8; u++)
            vv[u] = V2[(size_t)(uint32_t)(e[u] & 0xFFFFFFFFu) * 32 + lane];
        #pragma unroll
        for (int u = 0; u < 8; u++) {
            float w = __uint_as_float((uint32_t)(e[u] >> 32));
            ax = fmaf(w, vv[u].x, ax);
            ay = fmaf(w, vv[u].y, ay);
        }
    }
    for (; t < S; t++) {
        u64 e = selp[t];
        float w = __uint_as_float((uint32_t)(e >> 32));
        float2 v = V2[(size_t)(uint32_t)(e & 0xFFFFFFFFu) * 32 + lane];
        ax = fmaf(w, v.x, ax); ay = fmaf(w, v.y, ay);
    }

    float2* orow = (float2*)(Og + ((size_t)bh * SL + qg) * HD);
    orow[lane] = make_float2(ax * inv, ay * inv);
}

// ============================================================
// Fused kernel: bid-ordered pipeline  qk(0) | qk(1),sel(0) | ... | sel(63)
// ============================================================
__global__ void __launch_bounds__(256, 2)
fused_kernel(const float* __restrict__ Qg, const float* __restrict__ Kg,
             const float* __restrict__ Vg, float* __restrict__ Og)
{
    extern __shared__ char smem_raw[];
    const int bid = blockIdx.x;

    int role, bh, sub;
    if (bid < QK_BLOCKS) {
        role = 0; bh = 0; sub = bid;
    } else {
        int idx = bid - QK_BLOCKS;
        int g = idx / GRP, r = idx % GRP;
        if (g < NB * NH - 1 && r < QK_BLOCKS) { role = 0; bh = g + 1; sub = r; }
        else if (g < NB * NH - 1)             { role = 1; bh = g;     sub = r - QK_BLOCKS; }
        else                                  { role = 1; bh = NB * NH - 1; sub = r; }
    }

    if (role == 0) qk_body(smem_raw, Qg, Kg, bh, sub);
    else           sel_body(smem_raw, Vg, Og, bh, sub);
}

// ============================================================
extern "C" void kernel_launch(void* const* d_in, const int* in_sizes, int n_in,
                              void* d_out, int out_size) {
    (void)in_sizes; (void)n_in; (void)out_size;
    const float* Q = (const float*)d_in[0];
    const float* K = (const float*)d_in[1];
    const float* V = (const float*)d_in[2];
    float* O = (float*)d_out;

    cudaFuncSetAttribute(fused_kernel,
                         cudaFuncAttributeMaxDynamicSharedMemorySize, FUSED_SMEM);

    init_kernel<<<1, NB * NH>>>();

    const int nblocks = QK_BLOCKS + (NB * NH - 1) * GRP + SEL_BLOCKS;  // 25088
    fused_kernel<<<nblocks, 256, FUSED_SMEM>>>(Q, K, V, O);
}

// round 11
// speedup vs baseline: 2.0676x; 2.0676x over previous
#include <cuda_runtime.h>
#include <cstdint>

// Problem constants
#define NB 4
#define NH 16
#define SL 2048
#define HD 64
#define TOPKK 128
#define NEGMAX -3.402823466e38f

typedef unsigned long long u64;

// 1 GiB score-key scratch: [bh][q][k]
__device__ uint32_t g_keys[(size_t)NB * NH * SL * SL];

// order-preserving float <-> uint key (monotone increasing)
__device__ __forceinline__ uint32_t f2k(float f) {
    uint32_t b = __float_as_uint(f);
    return b ^ (0x80000000u | (uint32_t)((int32_t)b >> 31));
}
__device__ __forceinline__ float k2f(uint32_t k) {
    uint32_t b = k ^ ((k >> 31) ? 0x80000000u : 0xFFFFFFFFu);
    return __uint_as_float(b);
}

// ============================================================
// Kernel A: causal QK^T -> score keys (128x128 tiles, 8x8/thread)
// (unchanged — ~90% of FFMA roofline)
// ============================================================
#define TILE 128
#define APAD 132
#define A_SMEM (2 * 64 * APAD * 4)   // 67584 bytes

__global__ void __launch_bounds__(256, 2)
qk_kernel(const float* __restrict__ Qg, const float* __restrict__ Kg)
{
    extern __shared__ float sm[];
    float* Qs = sm;
    float* Ks = sm + 64 * APAD;

    int t = (gridDim.x - 1) - blockIdx.x;
    int qt = (int)((sqrtf(8.f * (float)t + 1.f) - 1.f) * 0.5f);
    while ((qt + 1) * (qt + 2) / 2 <= t) qt++;
    while (qt * (qt + 1) / 2 > t) qt--;
    int kt = t - qt * (qt + 1) / 2;

    const int bh = blockIdx.y;
    const int qbase = qt * TILE, kbase = kt * TILE;
    const int tid = threadIdx.x;

    const float* Qp = Qg + ((size_t)bh * SL + qbase) * HD;
    const float* Kp = Kg + ((size_t)bh * SL + kbase) * HD;

    #pragma unroll
    for (int it = 0; it < 8; it++) {
        int idx = it * 256 + tid;
        int r = idx >> 4, c = idx & 15;
        float4 v = ((const float4*)(Qp + (size_t)r * HD))[c];
        Qs[(4 * c + 0) * APAD + r] = v.x; Qs[(4 * c + 1) * APAD + r] = v.y;
        Qs[(4 * c + 2) * APAD + r] = v.z; Qs[(4 * c + 3) * APAD + r] = v.w;
        float4 w = ((const float4*)(Kp + (size_t)r * HD))[c];
        Ks[(4 * c + 0) * APAD + r] = w.x; Ks[(4 * c + 1) * APAD + r] = w.y;
        Ks[(4 * c + 2) * APAD + r] = w.z; Ks[(4 * c + 3) * APAD + r] = w.w;
    }
    __syncthreads();

    const int tx = tid & 15, ty = tid >> 4;
    const int q0 = ty * 8, k0 = tx * 8;

    float acc[8][8] = {};
    #pragma unroll 4
    for (int d = 0; d < 64; d++) {
        float a[8], b[8];
        *(float4*)&a[0] = *(const float4*)&Qs[d * APAD + q0];
        *(float4*)&a[4] = *(const float4*)&Qs[d * APAD + q0 + 4];
        *(float4*)&b[0] = *(const float4*)&Ks[d * APAD + k0];
        *(float4*)&b[4] = *(const float4*)&Ks[d * APAD + k0 + 4];
        #pragma unroll
        for (int i = 0; i < 8; i++)
            #pragma unroll
            for (int j = 0; j < 8; j++)
                acc[i][j] = fmaf(a[i], b[j], acc[i][j]);
    }

    const bool diag = (qt == kt);
    #pragma unroll
    for (int i = 0; i < 8; i++) {
        const int qg = qbase + q0 + i;
        uint32_t* row = g_keys + ((size_t)bh * SL + qg) * SL + kbase + k0;
        uint4 lo, hi;
        if (diag) {
            int ql = q0 + i;
            lo.x = f2k((k0     <= ql) ? acc[i][0] : NEGMAX);
            lo.y = f2k((k0 + 1 <= ql) ? acc[i][1] : NEGMAX);
            lo.z = f2k((k0 + 2 <= ql) ? acc[i][2] : NEGMAX);
            lo.w = f2k((k0 + 3 <= ql) ? acc[i][3] : NEGMAX);
            hi.x = f2k((k0 + 4 <= ql) ? acc[i][4] : NEGMAX);
            hi.y = f2k((k0 + 5 <= ql) ? acc[i][5] : NEGMAX);
            hi.z = f2k((k0 + 6 <= ql) ? acc[i][6] : NEGMAX);
            hi.w = f2k((k0 + 7 <= ql) ? acc[i][7] : NEGMAX);
        } else {
            lo.x = f2k(acc[i][0]); lo.y = f2k(acc[i][1]);
            lo.z = f2k(acc[i][2]); lo.w = f2k(acc[i][3]);
            hi.x = f2k(acc[i][4]); hi.y = f2k(acc[i][5]);
            hi.z = f2k(acc[i][6]); hi.w = f2k(acc[i][7]);
        }
        *(uint4*)row = lo;
        *(uint4*)(row + 4) = hi;
    }
}

// ============================================================
// Kernel B: streaming top-128 select + softmax + PV gather
// 4 CTAs/SM: CAP=576 -> 6.5KB/warp -> 52KB/CTA
// ============================================================
#define CAP 576
#define PRUNE_HI (CAP - 128)   // 448: max growth per check is 128
#define WSTRIDE 1664           // u32 per warp: buf u64[576] | hist 256 | selp u64[128]
#define B_SMEM (8 * WSTRIDE * 4)    // 53248 bytes

// descending bin scan: hist[256], rank r (1-based from top) -> bin B, r = rank within B
__device__ __forceinline__ void bin_scan(const uint32_t* hist, int lane, int& r, int& B) {
    const unsigned FULL = 0xFFFFFFFFu;
    int rev[8]; int s = 0;
    #pragma unroll
    for (int t = 0; t < 8; t++) { rev[t] = (int)hist[255 - (lane * 8 + t)]; s += rev[t]; }
    int inc = s;
    #pragma unroll
    for (int o = 1; o < 32; o <<= 1) {
        int v = __shfl_up_sync(FULL, inc, o);
        if (lane >= o) inc += v;
    }
    int pre = inc - s;
    int cum = pre, Bl = -1, rsub = 0;
    #pragma unroll
    for (int t = 0; t < 8; t++) {
        cum += rev[t];
        if (Bl < 0 && cum >= r) { Bl = 255 - (lane * 8 + t); rsub = r - (cum - rev[t]); }
    }
    unsigned bal = __ballot_sync(FULL, Bl >= 0);
    int src = __ffs(bal) - 1;
    B = __shfl_sync(FULL, Bl, src);
    r = __shfl_sync(FULL, rsub, src);
}

__global__ void __launch_bounds__(256, 4)
sel_kernel(const float* __restrict__ Vg, float* __restrict__ Og)
{
    extern __shared__ uint32_t smb[];
    const int tid = threadIdx.x;
    const int warp = tid >> 5, lane = tid & 31;
    const unsigned FULL = 0xFFFFFFFFu;
    const uint32_t lmask = (1u << lane) - 1u;
    const float scale = 0.125f;   // 64^-0.5

    uint32_t* wmem = smb + warp * WSTRIDE;
    u64* buf  = (u64*)wmem;                     // [CAP]
    uint32_t* hist = wmem + 2 * CAP;            // [256]
    u64* selp = (u64*)(wmem + 2 * CAP + 256);   // [128] packed (w_bits<<32 | idx)

    const int bh = blockIdx.y;
    const int qg = ((gridDim.x - 1) - blockIdx.x) * 8 + warp;   // heavy rows first
    const int n  = qg + 1;
    const uint32_t* krow = g_keys + ((size_t)bh * SL + qg) * SL;
    const uint4* kr4 = (const uint4*)krow;
    const int n4 = n >> 2;

    // threshold guess: E[s_128] - ~5 sigma of the order statistic
    uint32_t T0key = 0;
    if (n >= 512) {
        float lg = log2f((float)n * (1.0f / 128.0f));      // 2..4
        float t0 = 3.75f * lg - 4.5f;
        T0key = f2k(t0);
    }

    int cnt = 0, total = 0;
    u64 vmaxl = 0, vminl = ~(u64)0;
    for (int attempt = 0; ; attempt++) {
        uint32_t Tcur = attempt ? 0u : T0key;
        cnt = 0; total = 0;
        vmaxl = 0; vminl = ~(u64)0;

        for (int base = 0; base < n4; base += 32) {
            int i4 = base + lane;
            bool valid = i4 < n4;
            uint4 x = valid ? kr4[i4] : make_uint4(0, 0, 0, 0);
            #pragma unroll
            for (int c = 0; c < 4; c++) {
                uint32_t k = (c == 0) ? x.x : (c == 1) ? x.y : (c == 2) ? x.z : x.w;
                bool p = valid && (k >= Tcur);
                unsigned bal = __ballot_sync(FULL, p);
                if (p) {
                    int idx = 4 * i4 + c;
                    u64 v = ((u64)k << 32) | (uint32_t)(SL - 1 - idx);
                    buf[cnt + __popc(bal & lmask)] = v;
                    vmaxl = (v > vmaxl) ? v : vmaxl;
                    vminl = (v < vminl) ? v : vminl;
                }
                cnt   += __popc(bal);
                total += __popc(bal);
            }

            if (cnt > PRUNE_HI) {
                // EXACT prune: find buffer's 128th-largest u64 (unique), keep top 128
                u64 prefix = 0, pmask = 0;
                int rr = TOPKK;
                #pragma unroll 1
                for (int level = 7; level >= 0; level--) {
                    #pragma unroll
                    for (int t = 0; t < 8; t++) hist[lane + 32 * t] = 0;
                    __syncwarp();
                    for (int b2 = 0; b2 < cnt; b2 += 32) {
                        int i = b2 + lane;
                        bool valid2 = i < cnt;
                        u64 v = valid2 ? buf[i] : 0;
                        bool ok = valid2 && ((v & pmask) == prefix);
                        uint32_t bb = ok ? (uint32_t)((v >> (8 * level)) & 255) : 0x100u;
                        unsigned grp = __match_any_sync(FULL, bb);
                        if (ok && lane == __ffs(grp) - 1) atomicAdd(&hist[bb], __popc(grp));
                    }
                    __syncwarp();
                    int B; bin_scan(hist, lane, rr, B);
                    prefix |= ((u64)(uint32_t)B) << (8 * level);
                    pmask  |= ((u64)0xFF) << (8 * level);
                }
                const u64 T128 = prefix;
                int nc = 0;
                for (int b2 = 0; b2 < cnt; b2 += 32) {
                    int i = b2 + lane;
                    u64 v = (i < cnt) ? buf[i] : 0;
                    bool keep = (i < cnt) && (v >= T128);
                    unsigned bal = __ballot_sync(FULL, keep);
                    if (keep) buf[nc + __popc(bal & lmask)] = v;
                    nc += __popc(bal);
                }
                __syncwarp();
                cnt = nc;                       // exactly 128
                Tcur = (uint32_t)(T128 >> 32);  // admit equal keys (ties safe)
            }
        }
        // tail (n % 4)
        {
            int rem = n & 3;
            int i = (n4 << 2) + lane;
            uint32_t k = (lane < rem) ? krow[i] : 0u;
            bool p = (lane < rem) && (k >= Tcur);
            unsigned bal = __ballot_sync(FULL, p);
            if (p) {
                u64 v = ((u64)k << 32) | (uint32_t)(SL - 1 - i);
                buf[cnt + __popc(bal & lmask)] = v;
                vmaxl = (v > vmaxl) ? v : vmaxl;
                vminl = (v < vminl) ? v : vminl;
            }
            cnt   += __popc(bal);
            total += __popc(bal);
        }

        if (n <= TOPKK || total >= TOPKK) break;   // verified: top-128 fully captured
    }

    // ---- exact select on the buffer ----
    int selc = 0;
    float dsum = 0.f;

    if (n <= TOPKK) {
        for (int i = lane; i < cnt; i += 32) {
            u64 v = buf[i];
            float w = __expf(k2f((uint32_t)(v >> 32)) * scale);
            int idx = SL - 1 - (int)(uint32_t)(v & 0xFFFFFFFFu);
            selp[i] = ((u64)__float_as_uint(w) << 32) | (uint32_t)idx;
            dsum += w;
        }
        selc = cnt;
    } else {
        // warp-reduce vmax/vmin; skip identical-byte descent levels
        u64 vmaxW = vmaxl, vminW = vminl;
        #pragma unroll
        for (int o = 16; o > 0; o >>= 1) {
            u64 a = __shfl_xor_sync(FULL, vmaxW, o); if (a > vmaxW) vmaxW = a;
            u64 b = __shfl_xor_sync(FULL, vminW, o); if (b < vminW) vminW = b;
        }
        u64 diff = vmaxW ^ vminW;
        int level0 = (63 - __clzll(diff | 1)) >> 3;                 // 0..7
        const float ref = k2f((uint32_t)(vmaxW >> 32) & 0xFF000000u);

        int r = TOPKK;
        int mm = cnt;

        #pragma unroll 1
        for (int level = level0; level >= 0 && mm != r; level--) {
            #pragma unroll
            for (int t = 0; t < 8; t++) hist[lane + 32 * t] = 0;
            __syncwarp();
            for (int base = 0; base < mm; base += 32) {
                int i = base + lane;
                bool valid = i < mm;
                uint32_t bb = valid ? (uint32_t)((buf[i] >> (8 * level)) & 255) : 0x100u;
                unsigned grp = __match_any_sync(FULL, bb);
                if (valid && lane == __ffs(grp) - 1) atomicAdd(&hist[bb], __popc(grp));
            }
            __syncwarp();
            int B; bin_scan(hist, lane, r, B);

            int nb = 0;
            for (int base = 0; base < mm; base += 32) {
                int i = base + lane;
                u64 v = (i < mm) ? buf[i] : 0;
                int bb = (i < mm) ? (int)((v >> (8 * level)) & 255) : -1;
                bool sure = bb > B;
                bool inb  = bb == B;
                unsigned sbal = __ballot_sync(FULL, sure);
                unsigned bbal = __ballot_sync(FULL, inb);
                if (sure) {
                    float w = __expf((k2f((uint32_t)(v >> 32)) - ref) * scale);
                    int idx = SL - 1 - (int)(uint32_t)(v & 0xFFFFFFFFu);
                    selp[selc + __popc(sbal & lmask)] =
                        ((u64)__float_as_uint(w) << 32) | (uint32_t)idx;
                    dsum += w;
                }
                if (inb) buf[nb + __popc(bbal & lmask)] = v;
                selc += __popc(sbal);
                nb   += __popc(bbal);
            }
            mm = nb;
            __syncwarp();
        }

        // bucket holds exactly r elements (u64s unique) — take them all
        for (int i = lane; i < mm; i += 32) {
            u64 v = buf[i];
            float w = __expf((k2f((uint32_t)(v >> 32)) - ref) * scale);
            int idx = SL - 1 - (int)(uint32_t)(v & 0xFFFFFFFFu);
            selp[selc + i] = ((u64)__float_as_uint(w) << 32) | (uint32_t)idx;
            dsum += w;
        }
        selc += mm;
    }

    #pragma unroll
    for (int o = 16; o > 0; o >>= 1) dsum += __shfl_xor_sync(FULL, dsum, o);
    const float inv = 1.f / dsum;
    __syncwarp();

    // ---- PV gather: float2 per lane, 8-deep MLP ----
    const float2* V2 = (const float2*)(Vg + (size_t)bh * SL * HD);
    const int S = selc;
    float ax = 0.f, ay = 0.f;
    int t = 0;
    for (; t + 8 <= S; t += 8) {
        u64 e[8]; float2 vv[8];
        #pragma unroll
        for (int u = 0; u < 8; u++) e[u] = selp[t + u];
        #pragma unroll
        for (int u = 0; u < 8; u++)
            vv[u] = V2[(size_t)(uint32_t)(e[u] & 0xFFFFFFFFu) * 32 + lane];
        #pragma unroll
        for (int u = 0; u < 8; u++) {
            float w = __uint_as_float((uint32_t)(e[u] >> 32));
            ax = fmaf(w, vv[u].x, ax);
            ay = fmaf(w, vv[u].y, ay);
        }
    }
    for (; t < S; t++) {
        u64 e = selp[t];
        float w = __uint_as_float((uint32_t)(e >> 32));
        float2 v = V2[(size_t)(uint32_t)(e & 0xFFFFFFFFu) * 32 + lane];
        ax = fmaf(w, v.x, ax); ay = fmaf(w, v.y, ay);
    }

    float2* orow = (float2*)(Og + ((size_t)bh * SL + qg) * HD);
    orow[lane] = make_float2(ax * inv, ay * inv);
}

// ============================================================
extern "C" void kernel_launch(void* const* d_in, const int* in_sizes, int n_in,
                              void* d_out, int out_size) {
    (void)in_sizes; (void)n_in; (void)out_size;
    const float* Q = (const float*)d_in[0];
    const float* K = (const float*)d_in[1];
    const float* V = (const float*)d_in[2];
    float* O = (float*)d_out;

    cudaFuncSetAttribute(qk_kernel,  cudaFuncAttributeMaxDynamicSharedMemorySize, A_SMEM);
    cudaFuncSetAttribute(sel_kernel, cudaFuncAttributeMaxDynamicSharedMemorySize, B_SMEM);

    const int ntiles = (SL / TILE) * (SL / TILE + 1) / 2;   // 136
    dim3 gridA(ntiles, NB * NH);
    qk_kernel<<<gridA, 256, A_SMEM>>>(Q, K);

    dim3 gridB(SL / 8, NB * NH);    // (256, 64)
    sel_kernel<<<gridB, 256, B_SMEM>>>(V, O);
}

// round 12
// speedup vs baseline: 2.1579x; 1.0437x over previous
#include <cuda_runtime.h>
#include <cstdint>

// Problem constants
#define NB 4
#define NH 16
#define SL 2048
#define HD 64
#define TOPKK 128
#define NEGMAX -3.402823466e38f

typedef unsigned long long u64;

// 1 GiB score-key scratch: [bh][q][k]
__device__ uint32_t g_keys[(size_t)NB * NH * SL * SL];

// order-preserving float <-> uint key (monotone increasing)
__device__ __forceinline__ uint32_t f2k(float f) {
    uint32_t b = __float_as_uint(f);
    return b ^ (0x80000000u | (uint32_t)((int32_t)b >> 31));
}
__device__ __forceinline__ float k2f(uint32_t k) {
    uint32_t b = k ^ ((k >> 31) ? 0x80000000u : 0xFFFFFFFFu);
    return __uint_as_float(b);
}

// ============================================================
// Kernel A: causal QK^T -> score keys (128x128 tiles, 8x8/thread)
// (unchanged — ~90% of FFMA roofline)
// ============================================================
#define TILE 128
#define APAD 132
#define A_SMEM (2 * 64 * APAD * 4)   // 67584 bytes

__global__ void __launch_bounds__(256, 2)
qk_kernel(const float* __restrict__ Qg, const float* __restrict__ Kg)
{
    extern __shared__ float sm[];
    float* Qs = sm;
    float* Ks = sm + 64 * APAD;

    int t = (gridDim.x - 1) - blockIdx.x;
    int qt = (int)((sqrtf(8.f * (float)t + 1.f) - 1.f) * 0.5f);
    while ((qt + 1) * (qt + 2) / 2 <= t) qt++;
    while (qt * (qt + 1) / 2 > t) qt--;
    int kt = t - qt * (qt + 1) / 2;

    const int bh = blockIdx.y;
    const int qbase = qt * TILE, kbase = kt * TILE;
    const int tid = threadIdx.x;

    const float* Qp = Qg + ((size_t)bh * SL + qbase) * HD;
    const float* Kp = Kg + ((size_t)bh * SL + kbase) * HD;

    #pragma unroll
    for (int it = 0; it < 8; it++) {
        int idx = it * 256 + tid;
        int r = idx >> 4, c = idx & 15;
        float4 v = ((const float4*)(Qp + (size_t)r * HD))[c];
        Qs[(4 * c + 0) * APAD + r] = v.x; Qs[(4 * c + 1) * APAD + r] = v.y;
        Qs[(4 * c + 2) * APAD + r] = v.z; Qs[(4 * c + 3) * APAD + r] = v.w;
        float4 w = ((const float4*)(Kp + (size_t)r * HD))[c];
        Ks[(4 * c + 0) * APAD + r] = w.x; Ks[(4 * c + 1) * APAD + r] = w.y;
        Ks[(4 * c + 2) * APAD + r] = w.z; Ks[(4 * c + 3) * APAD + r] = w.w;
    }
    __syncthreads();

    const int tx = tid & 15, ty = tid >> 4;
    const int q0 = ty * 8, k0 = tx * 8;

    float acc[8][8] = {};
    #pragma unroll 4
    for (int d = 0; d < 64; d++) {
        float a[8], b[8];
        *(float4*)&a[0] = *(const float4*)&Qs[d * APAD + q0];
        *(float4*)&a[4] = *(const float4*)&Qs[d * APAD + q0 + 4];
        *(float4*)&b[0] = *(const float4*)&Ks[d * APAD + k0];
        *(float4*)&b[4] = *(const float4*)&Ks[d * APAD + k0 + 4];
        #pragma unroll
        for (int i = 0; i < 8; i++)
            #pragma unroll
            for (int j = 0; j < 8; j++)
                acc[i][j] = fmaf(a[i], b[j], acc[i][j]);
    }

    const bool diag = (qt == kt);
    #pragma unroll
    for (int i = 0; i < 8; i++) {
        const int qg = qbase + q0 + i;
        uint32_t* row = g_keys + ((size_t)bh * SL + qg) * SL + kbase + k0;
        uint4 lo, hi;
        if (diag) {
            int ql = q0 + i;
            lo.x = f2k((k0     <= ql) ? acc[i][0] : NEGMAX);
            lo.y = f2k((k0 + 1 <= ql) ? acc[i][1] : NEGMAX);
            lo.z = f2k((k0 + 2 <= ql) ? acc[i][2] : NEGMAX);
            lo.w = f2k((k0 + 3 <= ql) ? acc[i][3] : NEGMAX);
            hi.x = f2k((k0 + 4 <= ql) ? acc[i][4] : NEGMAX);
            hi.y = f2k((k0 + 5 <= ql) ? acc[i][5] : NEGMAX);
            hi.z = f2k((k0 + 6 <= ql) ? acc[i][6] : NEGMAX);
            hi.w = f2k((k0 + 7 <= ql) ? acc[i][7] : NEGMAX);
        } else {
            lo.x = f2k(acc[i][0]); lo.y = f2k(acc[i][1]);
            lo.z = f2k(acc[i][2]); lo.w = f2k(acc[i][3]);
            hi.x = f2k(acc[i][4]); hi.y = f2k(acc[i][5]);
            hi.z = f2k(acc[i][6]); hi.w = f2k(acc[i][7]);
        }
        *(uint4*)row = lo;
        *(uint4*)(row + 4) = hi;
    }
}

// ============================================================
// Kernel B: streaming top-128 select + softmax + PV gather
// ============================================================
#define CAP 576
#define PRUNE_HI (CAP - 128)   // 448
#define WSTRIDE 1664           // u32/warp: buf u64[576] | hist 256 | selp u64[128]
#define B_SMEM (8 * WSTRIDE * 4)    // 53248 bytes -> 4 CTAs/SM

// descending bin scan: hist[256], rank r (1-based from top) -> bin B, r = rank within B
__device__ __forceinline__ void bin_scan(const uint32_t* hist, int lane, int& r, int& B) {
    const unsigned FULL = 0xFFFFFFFFu;
    int rev[8]; int s = 0;
    #pragma unroll
    for (int t = 0; t < 8; t++) { rev[t] = (int)hist[255 - (lane * 8 + t)]; s += rev[t]; }
    int inc = s;
    #pragma unroll
    for (int o = 1; o < 32; o <<= 1) {
        int v = __shfl_up_sync(FULL, inc, o);
        if (lane >= o) inc += v;
    }
    int pre = inc - s;
    int cum = pre, Bl = -1, rsub = 0;
    #pragma unroll
    for (int t = 0; t < 8; t++) {
        cum += rev[t];
        if (Bl < 0 && cum >= r) { Bl = 255 - (lane * 8 + t); rsub = r - (cum - rev[t]); }
    }
    unsigned bal = __ballot_sync(FULL, Bl >= 0);
    int src = __ffs(bal) - 1;
    B = __shfl_sync(FULL, Bl, src);
    r = __shfl_sync(FULL, rsub, src);
}

// append the passing elements of one uint4 (warp-collective, uniform control)
__device__ __forceinline__ void stream4(uint4 x, bool valid, int i4, u64* buf,
                                        int& cnt, uint32_t Tcur, uint32_t lmask,
                                        u64& vmaxl, u64& vminl)
{
    const unsigned FULL = 0xFFFFFFFFu;
    #pragma unroll
    for (int c = 0; c < 4; c++) {
        uint32_t k = (c == 0) ? x.x : (c == 1) ? x.y : (c == 2) ? x.z : x.w;
        bool p = valid && (k >= Tcur);
        unsigned bal = __ballot_sync(FULL, p);
        if (p) {
            u64 v = ((u64)k << 32) | (uint32_t)(SL - 1 - (4 * i4 + c));
            buf[cnt + __popc(bal & lmask)] = v;
            vmaxl = (v > vmaxl) ? v : vmaxl;
            vminl = (v < vminl) ? v : vminl;
        }
        cnt += __popc(bal);
    }
}

// EXACT prune: keep the buffer's top 128 u64s (unique), raise threshold
__device__ __forceinline__ void prune128(u64* buf, uint32_t* hist, int& cnt,
                                         uint32_t& Tcur, int lane, uint32_t lmask)
{
    const unsigned FULL = 0xFFFFFFFFu;
    u64 prefix = 0, pmask = 0;
    int rr = TOPKK;
    #pragma unroll 1
    for (int level = 7; level >= 0; level--) {
        #pragma unroll
        for (int t = 0; t < 8; t++) hist[lane + 32 * t] = 0;
        __syncwarp();
        for (int b2 = 0; b2 < cnt; b2 += 32) {
            int i = b2 + lane;
            bool valid2 = i < cnt;
            u64 v = valid2 ? buf[i] : 0;
            bool ok = valid2 && ((v & pmask) == prefix);
            uint32_t bb = ok ? (uint32_t)((v >> (8 * level)) & 255) : 0x100u;
            unsigned grp = __match_any_sync(FULL, bb);
            if (ok && lane == __ffs(grp) - 1) atomicAdd(&hist[bb], __popc(grp));
        }
        __syncwarp();
        int B; bin_scan(hist, lane, rr, B);
        prefix |= ((u64)(uint32_t)B) << (8 * level);
        pmask  |= ((u64)0xFF) << (8 * level);
    }
    const u64 T128 = prefix;
    int nc = 0;
    for (int b2 = 0; b2 < cnt; b2 += 32) {
        int i = b2 + lane;
        u64 v = (i < cnt) ? buf[i] : 0;
        bool keep = (i < cnt) && (v >= T128);
        unsigned bal = __ballot_sync(FULL, keep);
        if (keep) buf[nc + __popc(bal & lmask)] = v;
        nc += __popc(bal);
    }
    __syncwarp();
    cnt = nc;                       // exactly 128
    Tcur = (uint32_t)(T128 >> 32);  // admit equal keys (ties safe)
}

__global__ void __launch_bounds__(256, 4)
sel_kernel(const float* __restrict__ Vg, float* __restrict__ Og)
{
    extern __shared__ uint32_t smb[];
    const int tid = threadIdx.x;
    const int warp = tid >> 5, lane = tid & 31;
    const unsigned FULL = 0xFFFFFFFFu;
    const uint32_t lmask = (1u << lane) - 1u;
    const float scale = 0.125f;   // 64^-0.5

    uint32_t* wmem = smb + warp * WSTRIDE;
    u64* buf  = (u64*)wmem;                     // [CAP]
    uint32_t* hist = wmem + 2 * CAP;            // [256]
    u64* selp = (u64*)(wmem + 2 * CAP + 256);   // [128] packed (w_bits<<32 | idx)

    const int bh = blockIdx.y;
    const int qg = ((gridDim.x - 1) - blockIdx.x) * 8 + warp;   // heavy rows first
    const int n  = qg + 1;
    const uint32_t* krow = g_keys + ((size_t)bh * SL + qg) * SL;
    const uint4* kr4 = (const uint4*)krow;
    const int n4 = n >> 2;

    // threshold guess for all n > 128: upper-quantile(128/n) - 5*sigma_orderstat
    uint32_t T0key = 0;
    if (n > TOPKK) {
        float p = 128.0f / (float)n;
        float z = normcdfinvf(1.0f - p);
        float pdf = 0.39894228f * __expf(-0.5f * z * z);
        float sos = 8.0f * sqrtf(p * (1.0f - p) / (float)n) / pdf;
        float t0 = 8.0f * z - 5.0f * sos;
        T0key = f2k(t0);
    }

    int cnt = 0;
    u64 vmaxl = 0, vminl = ~(u64)0;
    for (int attempt = 0; ; attempt++) {
        uint32_t Tcur = attempt ? 0u : T0key;
        cnt = 0;
        vmaxl = 0; vminl = ~(u64)0;

        for (int base = 0; base < n4; base += 64) {
            int ia = base + lane, ib = base + 32 + lane;
            bool va = ia < n4, vb = ib < n4;
            uint4 xa = va ? kr4[ia] : make_uint4(0, 0, 0, 0);
            uint4 xb = vb ? kr4[ib] : make_uint4(0, 0, 0, 0);

            stream4(xa, va, ia, buf, cnt, Tcur, lmask, vmaxl, vminl);
            if (cnt > PRUNE_HI) prune128(buf, hist, cnt, Tcur, lane, lmask);
            if (base + 32 < n4) {
                stream4(xb, vb, ib, buf, cnt, Tcur, lmask, vmaxl, vminl);
                if (cnt > PRUNE_HI) prune128(buf, hist, cnt, Tcur, lane, lmask);
            }
        }
        // tail (n % 4)
        {
            int rem = n & 3;
            int i = (n4 << 2) + lane;
            uint32_t k = (lane < rem) ? krow[i] : 0u;
            bool p = (lane < rem) && (k >= Tcur);
            unsigned bal = __ballot_sync(FULL, p);
            if (p) {
                u64 v = ((u64)k << 32) | (uint32_t)(SL - 1 - i);
                buf[cnt + __popc(bal & lmask)] = v;
                vmaxl = (v > vmaxl) ? v : vmaxl;
                vminl = (v < vminl) ? v : vminl;
            }
            cnt += __popc(bal);
        }

        // prune => cnt >= 128; otherwise cnt >= 128 certifies capture of top-128
        if (n <= TOPKK || cnt >= TOPKK) break;
    }

    // ---- exact select on the buffer ----
    int selc = 0;
    float dsum = 0.f;

    if (n <= TOPKK) {
        for (int i = lane; i < cnt; i += 32) {
            u64 v = buf[i];
            float w = __expf(k2f((uint32_t)(v >> 32)) * scale);
            int idx = SL - 1 - (int)(uint32_t)(v & 0xFFFFFFFFu);
            selp[i] = ((u64)__float_as_uint(w) << 32) | (uint32_t)idx;
            dsum += w;
        }
        selc = cnt;
    } else {
        // warp-reduce vmax/vmin; skip identical-byte descent levels
        u64 vmaxW = vmaxl, vminW = vminl;
        #pragma unroll
        for (int o = 16; o > 0; o >>= 1) {
            u64 a = __shfl_xor_sync(FULL, vmaxW, o); if (a > vmaxW) vmaxW = a;
            u64 b = __shfl_xor_sync(FULL, vminW, o); if (b < vminW) vminW = b;
        }
        u64 diff = vmaxW ^ vminW;
        int level0 = (63 - __clzll(diff | 1)) >> 3;                 // 0..7
        const float ref = k2f((uint32_t)(vmaxW >> 32) & 0xFF000000u);

        int r = TOPKK;
        int mm = cnt;

        #pragma unroll 1
        for (int level = level0; level >= 0 && mm != r; level--) {
            #pragma unroll
            for (int t = 0; t < 8; t++) hist[lane + 32 * t] = 0;
            __syncwarp();
            for (int base = 0; base < mm; base += 32) {
                int i = base + lane;
                bool valid = i < mm;
                uint32_t bb = valid ? (uint32_t)((buf[i] >> (8 * level)) & 255) : 0x100u;
                unsigned grp = __match_any_sync(FULL, bb);
                if (valid && lane == __ffs(grp) - 1) atomicAdd(&hist[bb], __popc(grp));
            }
            __syncwarp();
            int B; bin_scan(hist, lane, r, B);

            int nb = 0;
            for (int base = 0; base < mm; base += 32) {
                int i = base + lane;
                u64 v = (i < mm) ? buf[i] : 0;
                int bb = (i < mm) ? (int)((v >> (8 * level)) & 255) : -1;
                bool sure = bb > B;
                bool inb  = bb == B;
                unsigned sbal = __ballot_sync(FULL, sure);
                unsigned bbal = __ballot_sync(FULL, inb);
                if (sure) {
                    float w = __expf((k2f((uint32_t)(v >> 32)) - ref) * scale);
                    int idx = SL - 1 - (int)(uint32_t)(v & 0xFFFFFFFFu);
                    selp[selc + __popc(sbal & lmask)] =
                        ((u64)__float_as_uint(w) << 32) | (uint32_t)idx;
                    dsum += w;
                }
                if (inb) buf[nb + __popc(bbal & lmask)] = v;
                selc += __popc(sbal);
                nb   += __popc(bbal);
            }
            mm = nb;
            __syncwarp();
        }

        // bucket holds exactly r elements (u64s unique) — take them all
        for (int i = lane; i < mm; i += 32) {
            u64 v = buf[i];
            float w = __expf((k2f((uint32_t)(v >> 32)) - ref) * scale);
            int idx = SL - 1 - (int)(uint32_t)(v & 0xFFFFFFFFu);
            selp[selc + i] = ((u64)__float_as_uint(w) << 32) | (uint32_t)idx;
            dsum += w;
        }
        selc += mm;
    }

    #pragma unroll
    for (int o = 16; o > 0; o >>= 1) dsum += __shfl_xor_sync(FULL, dsum, o);
    const float inv = 1.f / dsum;

    // pad selp to even length (w=0, idx=0) for the 2-row gather
    if ((selc & 1) && lane == 0) selp[selc] = 0;
    const int T2 = (selc + 1) >> 1;
    __syncwarp();

    // ---- PV gather: 2 V-rows per step, float4 per lane, 4-deep MLP ----
    const float4* V4 = (const float4*)(Vg + (size_t)bh * SL * HD);
    const ulonglong2* sp2 = (const ulonglong2*)selp;
    const int half = lane >> 4, li = lane & 15;
    float ax = 0.f, ay = 0.f, az = 0.f, aw = 0.f;

    int t = 0;
    for (; t + 4 <= T2; t += 4) {
        ulonglong2 pp[4];
        #pragma unroll
        for (int u = 0; u < 4; u++) pp[u] = sp2[t + u];
        u64 e[4]; float4 vv[4];
        #pragma unroll
        for (int u = 0; u < 4; u++) {
            e[u] = half ? pp[u].y : pp[u].x;
            vv[u] = V4[(size_t)(uint32_t)(e[u] & 0xFFFFFFFFu) * 16 + li];
        }
        #pragma unroll
        for (int u = 0; u < 4; u++) {
            float w = __uint_as_float((uint32_t)(e[u] >> 32));
            ax = fmaf(w, vv[u].x, ax); ay = fmaf(w, vv[u].y, ay);
            az = fmaf(w, vv[u].z, az); aw = fmaf(w, vv[u].w, aw);
        }
    }
    for (; t < T2; t++) {
        ulonglong2 pp = sp2[t];
        u64 e = half ? pp.y : pp.x;
        float4 v = V4[(size_t)(uint32_t)(e & 0xFFFFFFFFu) * 16 + li];
        float w = __uint_as_float((uint32_t)(e >> 32));
        ax = fmaf(w, v.x, ax); ay = fmaf(w, v.y, ay);
        az = fmaf(w, v.z, az); aw = fmaf(w, v.w, aw);
    }

    // combine the two halves, lanes 0-15 write the output row
    ax += __shfl_xor_sync(FULL, ax, 16);
    ay += __shfl_xor_sync(FULL, ay, 16);
    az += __shfl_xor_sync(FULL, az, 16);
    aw += __shfl_xor_sync(FULL, aw, 16);
    if (half == 0) {
        float4* orow4 = (float4*)(Og + ((size_t)bh * SL + qg) * HD);
        orow4[li] = make_float4(ax * inv, ay * inv, az * inv, aw * inv);
    }
}

// ============================================================
extern "C" void kernel_launch(void* const* d_in, const int* in_sizes, int n_in,
                              void* d_out, int out_size) {
    (void)in_sizes; (void)n_in; (void)out_size;
    const float* Q = (const float*)d_in[0];
    const float* K = (const float*)d_in[1];
    const float* V = (const float*)d_in[2];
    float* O = (float*)d_out;

    cudaFuncSetAttribute(qk_kernel,  cudaFuncAttributeMaxDynamicSharedMemorySize, A_SMEM);
    cudaFuncSetAttribute(sel_kernel, cudaFuncAttributeMaxDynamicSharedMemorySize, B_SMEM);

    const int ntiles = (SL / TILE) * (SL / TILE + 1) / 2;   // 136
    dim3 gridA(ntiles, NB * NH);
    qk_kernel<<<gridA, 256, A_SMEM>>>(Q, K);

    dim3 gridB(SL / 8, NB * NH);    // (256, 64)
    sel_kernel<<<gridB, 256, B_SMEM>>>(V, O);
}

// round 14
// speedup vs baseline: 2.2386x; 1.0374x over previous
#include <cuda_runtime.h>
#include <cstdint>

// Problem constants
#define NB 4
#define NH 16
#define SL 2048
#define HD 64
#define TOPKK 128
#define NEGMAX -3.402823466e38f

typedef unsigned long long u64;

// 1 GiB score-key scratch: [bh][q][k]
__device__ uint32_t g_keys[(size_t)NB * NH * SL * SL];

// order-preserving float <-> uint key (monotone increasing)
__device__ __forceinline__ uint32_t f2k(float f) {
    uint32_t b = __float_as_uint(f);
    return b ^ (0x80000000u | (uint32_t)((int32_t)b >> 31));
}
__device__ __forceinline__ float k2f(uint32_t k) {
    uint32_t b = k ^ ((k >> 31) ? 0x80000000u : 0xFFFFFFFFu);
    return __uint_as_float(b);
}

// ============================================================
// Kernel A: causal QK^T via mma.sync tf32 (4-pass hi/lo), 128x128 tiles
// ============================================================
#define TILE 128
#define QPAD 68                          // floats per smem row (64 + 4 pad)
#define A_SMEM (4 * 128 * QPAD * 4)      // Qhi|Qlo|Khi|Klo = 139264 B

__device__ __forceinline__ void tf32_split(float x, uint32_t& hi, uint32_t& lo) {
    asm("cvt.rna.tf32.f32 %0, %1;" : "=r"(hi) : "f"(x));
    float l = x - __uint_as_float(hi);
    asm("cvt.rna.tf32.f32 %0, %1;" : "=r"(lo) : "f"(l));
}

__device__ __forceinline__ void mma_tf32(float* c, const uint32_t* a,
                                         uint32_t b0, uint32_t b1) {
    asm volatile(
        "mma.sync.aligned.m16n8k8.row.col.f32.tf32.tf32.f32 "
        "{%0,%1,%2,%3}, {%4,%5,%6,%7}, {%8,%9}, {%0,%1,%2,%3};"
        : "+f"(c[0]), "+f"(c[1]), "+f"(c[2]), "+f"(c[3])
        : "r"(a[0]), "r"(a[1]), "r"(a[2]), "r"(a[3]), "r"(b0), "r"(b1));
}

__global__ void __launch_bounds__(256, 1)
qk_kernel(const float* __restrict__ Qg, const float* __restrict__ Kg)
{
    extern __shared__ float sm[];
    float* Qhi = sm;
    float* Qlo = Qhi + 128 * QPAD;
    float* Khi = Qlo + 128 * QPAD;
    float* Klo = Khi + 128 * QPAD;

    // decode triangular tile (heavy first)
    int t = (gridDim.x - 1) - blockIdx.x;
    int qt = (int)((sqrtf(8.f * (float)t + 1.f) - 1.f) * 0.5f);
    while ((qt + 1) * (qt + 2) / 2 <= t) qt++;
    while (qt * (qt + 1) / 2 > t) qt--;
    int kt = t - qt * (qt + 1) / 2;

    const int bh = blockIdx.y;
    const int qbase = qt * TILE, kbase = kt * TILE;
    const int tid = threadIdx.x;

    const float* Qp = Qg + ((size_t)bh * SL + qbase) * HD;
    const float* Kp = Kg + ((size_t)bh * SL + kbase) * HD;

    // ---- stage Q,K as tf32 hi/lo (row-major, stride QPAD) ----
    #pragma unroll
    for (int it = 0; it < 8; it++) {
        int idx = it * 256 + tid;        // 0..2047
        int r = idx >> 4, c = idx & 15;  // row, float4 col
        float4 q = ((const float4*)(Qp + (size_t)r * HD))[c];
        uint4 qh, ql;
        tf32_split(q.x, qh.x, ql.x); tf32_split(q.y, qh.y, ql.y);
        tf32_split(q.z, qh.z, ql.z); tf32_split(q.w, qh.w, ql.w);
        *(uint4*)(Qhi + r * QPAD + 4 * c) = qh;
        *(uint4*)(Qlo + r * QPAD + 4 * c) = ql;
        float4 k = ((const float4*)(Kp + (size_t)r * HD))[c];
        uint4 kh, kl;
        tf32_split(k.x, kh.x, kl.x); tf32_split(k.y, kh.y, kl.y);
        tf32_split(k.z, kh.z, kl.z); tf32_split(k.w, kh.w, kl.w);
        *(uint4*)(Khi + r * QPAD + 4 * c) = kh;
        *(uint4*)(Klo + r * QPAD + 4 * c) = kl;
    }
    __syncthreads();

    // ---- warp tiling: 8 warps = 4(M) x 2(N); warp = 32 rows x 64 cols ----
    const int wid = tid >> 5, lane = tid & 31;
    const int warpM = wid >> 1, warpN = wid & 1;
    const int gid = lane >> 2, tg = lane & 3;
    const uint32_t* Qh32 = (const uint32_t*)Qhi;
    const uint32_t* Ql32 = (const uint32_t*)Qlo;
    const uint32_t* Kh32 = (const uint32_t*)Khi;
    const uint32_t* Kl32 = (const uint32_t*)Klo;

    float C[2][8][4];
    #pragma unroll
    for (int mt = 0; mt < 2; mt++)
        #pragma unroll
        for (int nt = 0; nt < 8; nt++)
            #pragma unroll
            for (int e = 0; e < 4; e++) C[mt][nt][e] = 0.f;

    #pragma unroll
    for (int ks = 0; ks < 8; ks++) {
        const int kk = ks * 8 + tg;
        uint32_t ahi[2][4], alo[2][4];
        #pragma unroll
        for (int mt = 0; mt < 2; mt++) {
            int r0 = warpM * 32 + mt * 16 + gid;
            ahi[mt][0] = Qh32[r0 * QPAD + kk];
            ahi[mt][1] = Qh32[(r0 + 8) * QPAD + kk];
            ahi[mt][2] = Qh32[r0 * QPAD + kk + 4];
            ahi[mt][3] = Qh32[(r0 + 8) * QPAD + kk + 4];
            alo[mt][0] = Ql32[r0 * QPAD + kk];
            alo[mt][1] = Ql32[(r0 + 8) * QPAD + kk];
            alo[mt][2] = Ql32[r0 * QPAD + kk + 4];
            alo[mt][3] = Ql32[(r0 + 8) * QPAD + kk + 4];
        }
        #pragma unroll
        for (int nt = 0; nt < 8; nt++) {
            int n0 = warpN * 64 + nt * 8 + gid;
            uint32_t bh0 = Kh32[n0 * QPAD + kk], bh1 = Kh32[n0 * QPAD + kk + 4];
            uint32_t bl0 = Kl32[n0 * QPAD + kk], bl1 = Kl32[n0 * QPAD + kk + 4];
            #pragma unroll
            for (int mt = 0; mt < 2; mt++) {
                // small terms first: lo*lo, hi*lo, lo*hi, then hi*hi
                mma_tf32(C[mt][nt], alo[mt], bl0, bl1);
                mma_tf32(C[mt][nt], ahi[mt], bl0, bl1);
                mma_tf32(C[mt][nt], alo[mt], bh0, bh1);
                mma_tf32(C[mt][nt], ahi[mt], bh0, bh1);
            }
        }
    }

    // ---- epilogue: causal mask (diag tiles) + f2k -> g_keys ----
    const bool diag = (qt == kt);
    #pragma unroll
    for (int mt = 0; mt < 2; mt++) {
        #pragma unroll
        for (int nt = 0; nt < 8; nt++) {
            int rl = warpM * 32 + mt * 16 + gid;      // local row (c0/c1)
            int cl = warpN * 64 + nt * 8 + 2 * tg;    // local col
            const float* c = C[mt][nt];
            uint32_t* p1 = g_keys + ((size_t)bh * SL + (qbase + rl)) * SL + kbase + cl;
            uint32_t* p2 = g_keys + ((size_t)bh * SL + (qbase + rl + 8)) * SL + kbase + cl;
            uint2 s1, s2;
            if (diag) {
                s1.x = f2k((cl     <= rl    ) ? c[0] : NEGMAX);
                s1.y = f2k((cl + 1 <= rl    ) ? c[1] : NEGMAX);
                s2.x = f2k((cl     <= rl + 8) ? c[2] : NEGMAX);
                s2.y = f2k((cl + 1 <= rl + 8) ? c[3] : NEGMAX);
            } else {
                s1.x = f2k(c[0]); s1.y = f2k(c[1]);
                s2.x = f2k(c[2]); s2.y = f2k(c[3]);
            }
            *(uint2*)p1 = s1;
            *(uint2*)p2 = s2;
        }
    }
}

// ============================================================
// Kernel B: streaming top-128 select + softmax + PV gather (unchanged R12)
// ============================================================
#define CAP 576
#define PRUNE_HI (CAP - 128)
#define WSTRIDE 1664
#define B_SMEM (8 * WSTRIDE * 4)

__device__ __forceinline__ void bin_scan(const uint32_t* hist, int lane, int& r, int& B) {
    const unsigned FULL = 0xFFFFFFFFu;
    int rev[8]; int s = 0;
    #pragma unroll
    for (int t = 0; t < 8; t++) { rev[t] = (int)hist[255 - (lane * 8 + t)]; s += rev[t]; }
    int inc = s;
    #pragma unroll
    for (int o = 1; o < 32; o <<= 1) {
        int v = __shfl_up_sync(FULL, inc, o);
        if (lane >= o) inc += v;
    }
    int pre = inc - s;
    int cum = pre, Bl = -1, rsub = 0;
    #pragma unroll
    for (int t = 0; t < 8; t++) {
        cum += rev[t];
        if (Bl < 0 && cum >= r) { Bl = 255 - (lane * 8 + t); rsub = r - (cum - rev[t]); }
    }
    unsigned bal = __ballot_sync(FULL, Bl >= 0);
    int src = __ffs(bal) - 1;
    B = __shfl_sync(FULL, Bl, src);
    r = __shfl_sync(FULL, rsub, src);
}

__device__ __forceinline__ void stream4(uint4 x, bool valid, int i4, u64* buf,
                                        int& cnt, uint32_t Tcur, uint32_t lmask,
                                        u64& vmaxl, u64& vminl)
{
    const unsigned FULL = 0xFFFFFFFFu;
    #pragma unroll
    for (int c = 0; c < 4; c++) {
        uint32_t k = (c == 0) ? x.x : (c == 1) ? x.y : (c == 2) ? x.z : x.w;
        bool p = valid && (k >= Tcur);
        unsigned bal = __ballot_sync(FULL, p);
        if (p) {
            u64 v = ((u64)k << 32) | (uint32_t)(SL - 1 - (4 * i4 + c));
            buf[cnt + __popc(bal & lmask)] = v;
            vmaxl = (v > vmaxl) ? v : vmaxl;
            vminl = (v < vminl) ? v : vminl;
        }
        cnt += __popc(bal);
    }
}

__device__ __forceinline__ void prune128(u64* buf, uint32_t* hist, int& cnt,
                                         uint32_t& Tcur, int lane, uint32_t lmask)
{
    const unsigned FULL = 0xFFFFFFFFu;
    u64 prefix = 0, pmask = 0;
    int rr = TOPKK;
    #pragma unroll 1
    for (int level = 7; level >= 0; level--) {
        #pragma unroll
        for (int t = 0; t < 8; t++) hist[lane + 32 * t] = 0;
        __syncwarp();
        for (int b2 = 0; b2 < cnt; b2 += 32) {
            int i = b2 + lane;
            bool valid2 = i < cnt;
            u64 v = valid2 ? buf[i] : 0;
            bool ok = valid2 && ((v & pmask) == prefix);
            uint32_t bb = ok ? (uint32_t)((v >> (8 * level)) & 255) : 0x100u;
            unsigned grp = __match_any_sync(FULL, bb);
            if (ok && lane == __ffs(grp) - 1) atomicAdd(&hist[bb], __popc(grp));
        }
        __syncwarp();
        int B; bin_scan(hist, lane, rr, B);
        prefix |= ((u64)(uint32_t)B) << (8 * level);
        pmask  |= ((u64)0xFF) << (8 * level);
    }
    const u64 T128 = prefix;
    int nc = 0;
    for (int b2 = 0; b2 < cnt; b2 += 32) {
        int i = b2 + lane;
        u64 v = (i < cnt) ? buf[i] : 0;
        bool keep = (i < cnt) && (v >= T128);
        unsigned bal = __ballot_sync(FULL, keep);
        if (keep) buf[nc + __popc(bal & lmask)] = v;
        nc += __popc(bal);
    }
    __syncwarp();
    cnt = nc;
    Tcur = (uint32_t)(T128 >> 32);
}

__global__ void __launch_bounds__(256, 4)
sel_kernel(const float* __restrict__ Vg, float* __restrict__ Og)
{
    extern __shared__ uint32_t smb2[];
    const int tid = threadIdx.x;
    const int warp = tid >> 5, lane = tid & 31;
    const unsigned FULL = 0xFFFFFFFFu;
    const uint32_t lmask = (1u << lane) - 1u;
    const float scale = 0.125f;

    uint32_t* wmem = smb2 + warp * WSTRIDE;
    u64* buf  = (u64*)wmem;
    uint32_t* hist = wmem + 2 * CAP;
    u64* selp = (u64*)(wmem + 2 * CAP + 256);

    const int bh = blockIdx.y;
    const int qg = ((gridDim.x - 1) - blockIdx.x) * 8 + warp;
    const int n  = qg + 1;
    const uint32_t* krow = g_keys + ((size_t)bh * SL + qg) * SL;
    const uint4* kr4 = (const uint4*)krow;
    const int n4 = n >> 2;

    uint32_t T0key = 0;
    if (n > TOPKK) {
        float p = 128.0f / (float)n;
        float z = normcdfinvf(1.0f - p);
        float pdf = 0.39894228f * __expf(-0.5f * z * z);
        float sos = 8.0f * sqrtf(p * (1.0f - p) / (float)n) / pdf;
        float t0 = 8.0f * z - 5.0f * sos;
        T0key = f2k(t0);
    }

    int cnt = 0;
    u64 vmaxl = 0, vminl = ~(u64)0;
    for (int attempt = 0; ; attempt++) {
        uint32_t Tcur = attempt ? 0u : T0key;
        cnt = 0;
        vmaxl = 0; vminl = ~(u64)0;

        for (int base = 0; base < n4; base += 64) {
            int ia = base + lane, ib = base + 32 + lane;
            bool va = ia < n4, vb = ib < n4;
            uint4 xa = va ? kr4[ia] : make_uint4(0, 0, 0, 0);
            uint4 xb = vb ? kr4[ib] : make_uint4(0, 0, 0, 0);

            stream4(xa, va, ia, buf, cnt, Tcur, lmask, vmaxl, vminl);
            if (cnt > PRUNE_HI) prune128(buf, hist, cnt, Tcur, lane, lmask);
            if (base + 32 < n4) {
                stream4(xb, vb, ib, buf, cnt, Tcur, lmask, vmaxl, vminl);
                if (cnt > PRUNE_HI) prune128(buf, hist, cnt, Tcur, lane, lmask);
            }
        }
        {
            int rem = n & 3;
            int i = (n4 << 2) + lane;
            uint32_t k = (lane < rem) ? krow[i] : 0u;
            bool p = (lane < rem) && (k >= Tcur);
            unsigned bal = __ballot_sync(FULL, p);
            if (p) {
                u64 v = ((u64)k << 32) | (uint32_t)(SL - 1 - i);
                buf[cnt + __popc(bal & lmask)] = v;
                vmaxl = (v > vmaxl) ? v : vmaxl;
                vminl = (v < vminl) ? v : vminl;
            }
            cnt += __popc(bal);
        }

        if (n <= TOPKK || cnt >= TOPKK) break;
    }

    int selc = 0;
    float dsum = 0.f;

    if (n <= TOPKK) {
        for (int i = lane; i < cnt; i += 32) {
            u64 v = buf[i];
            float w = __expf(k2f((uint32_t)(v >> 32)) * scale);
            int idx = SL - 1 - (int)(uint32_t)(v & 0xFFFFFFFFu);
            selp[i] = ((u64)__float_as_uint(w) << 32) | (uint32_t)idx;
            dsum += w;
        }
        selc = cnt;
    } else {
        u64 vmaxW = vmaxl, vminW = vminl;
        #pragma unroll
        for (int o = 16; o > 0; o >>= 1) {
            u64 a = __shfl_xor_sync(FULL, vmaxW, o); if (a > vmaxW) vmaxW = a;
            u64 b = __shfl_xor_sync(FULL, vminW, o); if (b < vminW) vminW = b;
        }
        u64 diff = vmaxW ^ vminW;
        int level0 = (63 - __clzll(diff | 1)) >> 3;
        const float ref = k2f((uint32_t)(vmaxW >> 32) & 0xFF000000u);

        int r = TOPKK;
        int mm = cnt;

        #pragma unroll 1
        for (int level = level0; level >= 0 && mm != r; level--) {
            #pragma unroll
            for (int t = 0; t < 8; t++) hist[lane + 32 * t] = 0;
            __syncwarp();
            for (int base = 0; base < mm; base += 32) {
                int i = base + lane;
                bool valid = i < mm;
                uint32_t bb = valid ? (uint32_t)((buf[i] >> (8 * level)) & 255) : 0x100u;
                unsigned grp = __match_any_sync(FULL, bb);
                if (valid && lane == __ffs(grp) - 1) atomicAdd(&hist[bb], __popc(grp));
            }
            __syncwarp();
            int B; bin_scan(hist, lane, r, B);

            int nb = 0;
            for (int base = 0; base < mm; base += 32) {
                int i = base + lane;
                u64 v = (i < mm) ? buf[i] : 0;
                int bb = (i < mm) ? (int)((v >> (8 * level)) & 255) : -1;
                bool sure = bb > B;
                bool inb  = bb == B;
                unsigned sbal = __ballot_sync(FULL, sure);
                unsigned bbal = __ballot_sync(FULL, inb);
                if (sure) {
                    float w = __expf((k2f((uint32_t)(v >> 32)) - ref) * scale);
                    int idx = SL - 1 - (int)(uint32_t)(v & 0xFFFFFFFFu);
                    selp[selc + __popc(sbal & lmask)] =
                        ((u64)__float_as_uint(w) << 32) | (uint32_t)idx;
                    dsum += w;
                }
                if (inb) buf[nb + __popc(bbal & lmask)] = v;
                selc += __popc(sbal);
                nb   += __popc(bbal);
            }
            mm = nb;
            __syncwarp();
        }

        for (int i = lane; i < mm; i += 32) {
            u64 v = buf[i];
            float w = __expf((k2f((uint32_t)(v >> 32)) - ref) * scale);
            int idx = SL - 1 - (int)(uint32_t)(v & 0xFFFFFFFFu);
            selp[selc + i] = ((u64)__float_as_uint(w) << 32) | (uint32_t)idx;
            dsum += w;
        }
        selc += mm;
    }

    #pragma unroll
    for (int o = 16; o > 0; o >>= 1) dsum += __shfl_xor_sync(FULL, dsum, o);
    const float inv = 1.f / dsum;

    if ((selc & 1) && lane == 0) selp[selc] = 0;
    const int T2 = (selc + 1) >> 1;
    __syncwarp();

    const float4* V4 = (const float4*)(Vg + (size_t)bh * SL * HD);
    const ulonglong2* sp2 = (const ulonglong2*)selp;
    const int half = lane >> 4, li = lane & 15;
    float ax = 0.f, ay = 0.f, az = 0.f, aw = 0.f;

    int t = 0;
    for (; t + 4 <= T2; t += 4) {
        ulonglong2 pp[4];
        #pragma unroll
        for (int u = 0; u < 4; u++) pp[u] = sp2[t + u];
        u64 e[4]; float4 vv[4];
        #pragma unroll
        for (int u = 0; u < 4; u++) {
            e[u] = half ? pp[u].y : pp[u].x;
            vv[u] = V4[(size_t)(uint32_t)(e[u] & 0xFFFFFFFFu) * 16 + li];
        }
        #pragma unroll
        for (int u = 0; u < 4; u++) {
            float w = __uint_as_float((uint32_t)(e[u] >> 32));
            ax = fmaf(w, vv[u].x, ax); ay = fmaf(w, vv[u].y, ay);
            az = fmaf(w, vv[u].z, az); aw = fmaf(w, vv[u].w, aw);
        }
    }
    for (; t < T2; t++) {
        ulonglong2 pp = sp2[t];
        u64 e = half ? pp.y : pp.x;
        float4 v = V4[(size_t)(uint32_t)(e & 0xFFFFFFFFu) * 16 + li];
        float w = __uint_as_float((uint32_t)(e >> 32));
        ax = fmaf(w, v.x, ax); ay = fmaf(w, v.y, ay);
        az = fmaf(w, v.z, az); aw = fmaf(w, v.w, aw);
    }

    ax += __shfl_xor_sync(FULL, ax, 16);
    ay += __shfl_xor_sync(FULL, ay, 16);
    az += __shfl_xor_sync(FULL, az, 16);
    aw += __shfl_xor_sync(FULL, aw, 16);
    if (half == 0) {
        float4* orow4 = (float4*)(Og + ((size_t)bh * SL + qg) * HD);
        orow4[li] = make_float4(ax * inv, ay * inv, az * inv, aw * inv);
    }
}

// ============================================================
extern "C" void kernel_launch(void* const* d_in, const int* in_sizes, int n_in,
                              void* d_out, int out_size) {
    (void)in_sizes; (void)n_in; (void)out_size;
    const float* Q = (const float*)d_in[0];
    const float* K = (const float*)d_in[1];
    const float* V = (const float*)d_in[2];
    float* O = (float*)d_out;

    cudaFuncSetAttribute(qk_kernel,  cudaFuncAttributeMaxDynamicSharedMemorySize, A_SMEM);
    cudaFuncSetAttribute(sel_kernel, cudaFuncAttributeMaxDynamicSharedMemorySize, B_SMEM);

    const int ntiles = (SL / TILE) * (SL / TILE + 1) / 2;   // 136
    dim3 gridA(ntiles, NB * NH);
    qk_kernel<<<gridA, 256, A_SMEM>>>(Q, K);

    dim3 gridB(SL / 8, NB * NH);    // (256, 64)
    sel_kernel<<<gridB, 256, B_SMEM>>>(V, O);
}